// round 4
// baseline (speedup 1.0000x reference)
#include <cuda_runtime.h>
#include <math.h>

// ---------------- problem constants ----------------
#define Dm   896
#define Hh   8
#define HDd  112
#define Pp   196
#define Ff   32
#define LQ   1568           // M * P
#define LK   6272           // F * P
#define D4   3584           // 4 * D

// ---------------- scratch (device globals; no allocs allowed) ----------------
__device__ __align__(256) float g_Q  [LQ * Dm];
__device__ __align__(256) float g_K  [LK * Dm + 256];
__device__ __align__(256) float g_V  [LK * Dm + 256];
__device__ __align__(256) float g_S  [(size_t)Hh * LQ * LK];     // scores / probs, 314 MB
__device__ __align__(256) float g_CTX[LQ * Dm + 256];
__device__ __align__(256) float g_T1 [LQ * Dm];
__device__ __align__(256) float g_AO [LQ * Dm];
__device__ __align__(256) float g_HID[(size_t)LQ * D4 + 256];
__device__ __align__(256) float g_ASUM[LK];

// ---------------- reductions ----------------
__device__ __forceinline__ float warp_reduce_sum(float v) {
#pragma unroll
    for (int o = 16; o > 0; o >>= 1) v += __shfl_down_sync(0xffffffffu, v, o);
    return v;
}
__device__ __forceinline__ float warp_reduce_max(float v) {
#pragma unroll
    for (int o = 16; o > 0; o >>= 1) v = fmaxf(v, __shfl_down_sync(0xffffffffu, v, o));
    return v;
}
__device__ __forceinline__ float block_reduce_sum(float v, float* sred) {
    __syncthreads();
    v = warp_reduce_sum(v);
    if ((threadIdx.x & 31) == 0) sred[threadIdx.x >> 5] = v;
    __syncthreads();
    int nw = (blockDim.x + 31) >> 5;
    if (threadIdx.x < 32) {
        float x = (threadIdx.x < nw) ? sred[threadIdx.x] : 0.f;
        x = warp_reduce_sum(x);
        if (threadIdx.x == 0) sred[0] = x;
    }
    __syncthreads();
    return sred[0];
}
__device__ __forceinline__ float block_reduce_max(float v, float* sred) {
    __syncthreads();
    v = warp_reduce_max(v);
    if ((threadIdx.x & 31) == 0) sred[threadIdx.x >> 5] = v;
    __syncthreads();
    int nw = (blockDim.x + 31) >> 5;
    if (threadIdx.x < 32) {
        float x = (threadIdx.x < nw) ? sred[threadIdx.x] : -1e30f;
        x = warp_reduce_max(x);
        if (threadIdx.x == 0) sred[0] = x;
    }
    __syncthreads();
    return sred[0];
}

// ---------------- utility kernels ----------------
__global__ void zero_kernel(float* __restrict__ p, int n) {
    int i = blockIdx.x * blockDim.x + threadIdx.x;
    if (i < n) p[i] = 0.f;
}

// ---------------- SGEMM: 128x128x8, 256 threads, 8x8/thread ----------------
#define BM 128
#define BN 128
#define BK 8

// C[batch] = act(alpha * A[batch] @ B[batch] + bias + res)
// A row-major [M,K] (lda), B row-major [K,N] (ldb).
// nsplit>1: K is split across blockIdx.z%nsplit; partial sums atomicAdd into a
// pre-zeroed C; bias/res contributed only by split 0; relu must be 0 then.
__global__ __launch_bounds__(256, 2)
void gemm_nn(const float* __restrict__ A, int lda, long long sAz,
             const float* __restrict__ B, int ldb, long long sBz,
             float* __restrict__ C, int ldc, long long sCz,
             int Md, int Nd, int Kd, int nsplit,
             const float* __restrict__ bias,
             const float* __restrict__ res, int ldres,
             float alpha, int relu)
{
    __shared__ float As[BK][BM + 4];
    __shared__ float Bs[BK][BN + 4];

    const int batch = blockIdx.z / nsplit;
    const int split = blockIdx.z % nsplit;
    A += (long long)batch * sAz;
    B += (long long)batch * sBz;
    C += (long long)batch * sCz;

    const int kLen = Kd / nsplit;
    const int kBeg = split * kLen;
    const int kEnd = kBeg + kLen;

    const int m0 = blockIdx.y * BM;
    const int n0 = blockIdx.x * BN;
    const int tid = threadIdx.x;
    const int tx = tid & 15;
    const int ty = tid >> 4;

    const int arow = tid >> 1;
    const int acol = (tid & 1) << 2;
    const int brow = tid >> 5;
    const int bcol = (tid & 31) << 2;

    float acc[8][8];
#pragma unroll
    for (int i = 0; i < 8; i++)
#pragma unroll
        for (int j = 0; j < 8; j++) acc[i][j] = 0.f;

    const bool arow_ok = (m0 + arow) < Md;
    const float* Abase = A + (long long)(m0 + arow) * lda + acol;

    for (int k0 = kBeg; k0 < kEnd; k0 += BK) {
        float4 av = arow_ok ? *reinterpret_cast<const float4*>(Abase + k0)
                            : make_float4(0.f, 0.f, 0.f, 0.f);
        As[acol + 0][arow] = av.x;
        As[acol + 1][arow] = av.y;
        As[acol + 2][arow] = av.z;
        As[acol + 3][arow] = av.w;
        float4 bv = *reinterpret_cast<const float4*>(
            &B[(long long)(k0 + brow) * ldb + n0 + bcol]);
        *reinterpret_cast<float4*>(&Bs[brow][bcol]) = bv;
        __syncthreads();
#pragma unroll
        for (int kk = 0; kk < BK; kk++) {
            float ra[8], rb[8];
            *reinterpret_cast<float4*>(&ra[0]) = *reinterpret_cast<const float4*>(&As[kk][ty * 8]);
            *reinterpret_cast<float4*>(&ra[4]) = *reinterpret_cast<const float4*>(&As[kk][ty * 8 + 4]);
            *reinterpret_cast<float4*>(&rb[0]) = *reinterpret_cast<const float4*>(&Bs[kk][tx * 8]);
            *reinterpret_cast<float4*>(&rb[4]) = *reinterpret_cast<const float4*>(&Bs[kk][tx * 8 + 4]);
#pragma unroll
            for (int i = 0; i < 8; i++)
#pragma unroll
                for (int j = 0; j < 8; j++)
                    acc[i][j] = fmaf(ra[i], rb[j], acc[i][j]);
        }
        __syncthreads();
    }

#pragma unroll
    for (int i = 0; i < 8; i++) {
        int m = m0 + ty * 8 + i;
        if (m >= Md) continue;
#pragma unroll
        for (int j = 0; j < 8; j++) {
            int n = n0 + tx * 8 + j;
            if (n >= Nd) continue;
            float v = acc[i][j] * alpha;
            if (nsplit > 1) {
                if (split == 0) {
                    if (bias) v += bias[n];
                    if (res)  v += res[(long long)m * ldres + n];
                }
                atomicAdd(&C[(long long)m * ldc + n], v);
            } else {
                if (bias) v += bias[n];
                if (res)  v += res[(long long)m * ldres + n];
                if (relu) v = fmaxf(v, 0.f);
                C[(long long)m * ldc + n] = v;
            }
        }
    }
}

// C[batch] = alpha * A[batch] @ B[batch]^T ; B row-major [N,K] (ldb)
__global__ __launch_bounds__(256, 2)
void gemm_nt(const float* __restrict__ A, int lda, long long sAz,
             const float* __restrict__ B, int ldb, long long sBz,
             float* __restrict__ C, int ldc, long long sCz,
             int Md, int Nd, int Kd, float alpha)
{
    __shared__ float As[BK][BM + 4];
    __shared__ float Bs[BK][BN + 4];

    const int batch = blockIdx.z;
    A += (long long)batch * sAz;
    B += (long long)batch * sBz;
    C += (long long)batch * sCz;

    const int m0 = blockIdx.y * BM;
    const int n0 = blockIdx.x * BN;
    const int tid = threadIdx.x;
    const int tx = tid & 15;
    const int ty = tid >> 4;

    const int arow = tid >> 1;
    const int acol = (tid & 1) << 2;

    float acc[8][8];
#pragma unroll
    for (int i = 0; i < 8; i++)
#pragma unroll
        for (int j = 0; j < 8; j++) acc[i][j] = 0.f;

    const bool arow_ok = (m0 + arow) < Md;
    const bool brow_ok = (n0 + arow) < Nd;
    const float* Abase = A + (long long)(m0 + arow) * lda + acol;
    const float* Bbase = B + (long long)(n0 + arow) * ldb + acol;

    for (int k0 = 0; k0 < Kd; k0 += BK) {
        float4 av = arow_ok ? *reinterpret_cast<const float4*>(Abase + k0)
                            : make_float4(0.f, 0.f, 0.f, 0.f);
        As[acol + 0][arow] = av.x;
        As[acol + 1][arow] = av.y;
        As[acol + 2][arow] = av.z;
        As[acol + 3][arow] = av.w;
        float4 bv = brow_ok ? *reinterpret_cast<const float4*>(Bbase + k0)
                            : make_float4(0.f, 0.f, 0.f, 0.f);
        Bs[acol + 0][arow] = bv.x;
        Bs[acol + 1][arow] = bv.y;
        Bs[acol + 2][arow] = bv.z;
        Bs[acol + 3][arow] = bv.w;
        __syncthreads();
#pragma unroll
        for (int kk = 0; kk < BK; kk++) {
            float ra[8], rb[8];
            *reinterpret_cast<float4*>(&ra[0]) = *reinterpret_cast<const float4*>(&As[kk][ty * 8]);
            *reinterpret_cast<float4*>(&ra[4]) = *reinterpret_cast<const float4*>(&As[kk][ty * 8 + 4]);
            *reinterpret_cast<float4*>(&rb[0]) = *reinterpret_cast<const float4*>(&Bs[kk][tx * 8]);
            *reinterpret_cast<float4*>(&rb[4]) = *reinterpret_cast<const float4*>(&Bs[kk][tx * 8 + 4]);
#pragma unroll
            for (int i = 0; i < 8; i++)
#pragma unroll
                for (int j = 0; j < 8; j++)
                    acc[i][j] = fmaf(ra[i], rb[j], acc[i][j]);
        }
        __syncthreads();
    }

#pragma unroll
    for (int i = 0; i < 8; i++) {
        int m = m0 + ty * 8 + i;
        if (m >= Md) continue;
#pragma unroll
        for (int j = 0; j < 8; j++) {
            int n = n0 + tx * 8 + j;
            if (n >= Nd) continue;
            C[(long long)m * ldc + n] = acc[i][j] * alpha;
        }
    }
}

// ---------------- softmax over rows of S (rowlen = LK), in place ----------------
__global__ __launch_bounds__(256)
void softmax_kernel(float* __restrict__ S)
{
    __shared__ float buf[LK];
    __shared__ float sred[32];
    float* p = S + (size_t)blockIdx.x * LK;
    const int t = threadIdx.x;

    float mx = -1e30f;
    for (int i = t; i < LK; i += 256) {
        float v = p[i];
        buf[i] = v;
        mx = fmaxf(mx, v);
    }
    mx = block_reduce_max(mx, sred);

    float sum = 0.f;
    for (int i = t; i < LK; i += 256) {
        float e = expf(buf[i] - mx);
        buf[i] = e;
        sum += e;
    }
    sum = block_reduce_sum(sum, sred);
    float inv = 1.f / sum;
    for (int i = t; i < LK; i += 256) p[i] = buf[i] * inv;
}

// ---------------- column sum of probs -> attn_sum (atomic partials) ----------------
__global__ void colsum_kernel(const float* __restrict__ S, float* __restrict__ asum,
                              int rows_per_chunk, int total_rows)
{
    int k = blockIdx.x * blockDim.x + threadIdx.x;
    if (k >= LK) return;
    int r0 = blockIdx.y * rows_per_chunk;
    int r1 = min(r0 + rows_per_chunk, total_rows);
    float s0 = 0.f, s1 = 0.f, s2 = 0.f, s3 = 0.f;
    int r = r0;
    for (; r + 4 <= r1; r += 4) {
        s0 += S[(size_t)(r + 0) * LK + k];
        s1 += S[(size_t)(r + 1) * LK + k];
        s2 += S[(size_t)(r + 2) * LK + k];
        s3 += S[(size_t)(r + 3) * LK + k];
    }
    for (; r < r1; r++) s0 += S[(size_t)r * LK + k];
    atomicAdd(&asum[k], (s0 + s1) + (s2 + s3));
}

// ---------------- layernorm over D=896 per row ----------------
__global__ __launch_bounds__(224)
void layernorm_kernel(const float* __restrict__ X, const float* __restrict__ g,
                      const float* __restrict__ b, float* __restrict__ Y)
{
    __shared__ float sred[32];
    const float* x = X + (size_t)blockIdx.x * Dm;
    float*       y = Y + (size_t)blockIdx.x * Dm;
    const int t = threadIdx.x;

    float4 xv = *reinterpret_cast<const float4*>(x + t * 4);
    float s = (xv.x + xv.y) + (xv.z + xv.w);
    s = block_reduce_sum(s, sred);
    float mu = s * (1.0f / Dm);

    float d0 = xv.x - mu, d1 = xv.y - mu, d2 = xv.z - mu, d3 = xv.w - mu;
    float sq = (d0 * d0 + d1 * d1) + (d2 * d2 + d3 * d3);
    sq = block_reduce_sum(sq, sred);
    float inv = rsqrtf(sq * (1.0f / Dm) + 1e-12f);

    float4 gv = *reinterpret_cast<const float4*>(g + t * 4);
    float4 bv = *reinterpret_cast<const float4*>(b + t * 4);
    float4 ov;
    ov.x = d0 * inv * gv.x + bv.x;
    ov.y = d1 * inv * gv.y + bv.y;
    ov.z = d2 * inv * gv.z + bv.z;
    ov.w = d3 * inv * gv.w + bv.w;
    *reinterpret_cast<float4*>(y + t * 4) = ov;
}

// ---------------- frame scores: mean over 196 per frame ----------------
__global__ void frame_kernel(const float* __restrict__ asum, float* __restrict__ out)
{
    __shared__ float red[256];
    int f = blockIdx.x;
    float s = 0.f;
    for (int i = threadIdx.x; i < Pp; i += blockDim.x) s += asum[f * Pp + i];
    red[threadIdx.x] = s;
    __syncthreads();
    for (int o = 128; o > 0; o >>= 1) {
        if (threadIdx.x < o) red[threadIdx.x] += red[threadIdx.x + o];
        __syncthreads();
    }
    if (threadIdx.x == 0) out[f] = red[0] * (1.0f / Pp);
}

// ---------------- host orchestration ----------------
extern "C" void kernel_launch(void* const* d_in, const int* in_sizes, int n_in,
                              void* d_out, int out_size)
{
    const float* img  = (const float*)d_in[0];
    const float* mem  = (const float*)d_in[1];
    const float* qW   = (const float*)d_in[2];
    const float* qb   = (const float*)d_in[3];
    const float* kW   = (const float*)d_in[4];
    const float* kb   = (const float*)d_in[5];
    const float* vW   = (const float*)d_in[6];
    const float* vb   = (const float*)d_in[7];
    const float* oW   = (const float*)d_in[8];
    const float* ob   = (const float*)d_in[9];
    const float* ln1g = (const float*)d_in[10];
    const float* ln1b = (const float*)d_in[11];
    const float* mW   = (const float*)d_in[12];
    const float* mb   = (const float*)d_in[13];
    const float* pW   = (const float*)d_in[14];
    const float* pb   = (const float*)d_in[15];
    const float* ln2g = (const float*)d_in[16];
    const float* ln2b = (const float*)d_in[17];
    float* out = (float*)d_out;

    float *Qp, *Kp, *Vp, *Sp, *CTXp, *T1p, *AOp, *HIDp, *ASUMp;
    cudaGetSymbolAddress((void**)&Qp,   g_Q);
    cudaGetSymbolAddress((void**)&Kp,   g_K);
    cudaGetSymbolAddress((void**)&Vp,   g_V);
    cudaGetSymbolAddress((void**)&Sp,   g_S);
    cudaGetSymbolAddress((void**)&CTXp, g_CTX);
    cudaGetSymbolAddress((void**)&T1p,  g_T1);
    cudaGetSymbolAddress((void**)&AOp,  g_AO);
    cudaGetSymbolAddress((void**)&HIDp, g_HID);
    cudaGetSymbolAddress((void**)&ASUMp,g_ASUM);

    const int mtiles = (LQ + BM - 1) / BM;   // 13
    const float inv_sqrt_hd = 0.09449111825230681f;  // 1/sqrt(112)

    // zero the atomic-accumulated buffers
    zero_kernel<<<(LQ * Dm + 255) / 256, 256>>>(Qp,   LQ * Dm);
    zero_kernel<<<(LQ * Dm + 255) / 256, 256>>>(CTXp, LQ * Dm);
    zero_kernel<<<(LQ * Dm + 255) / 256, 256>>>(T1p,  LQ * Dm);
    zero_kernel<<<(LK + 255) / 256, 256>>>(ASUMp, LK);

    // Q = mem @ qW + qb   (split-K=2 to fill SMs)
    gemm_nn<<<dim3(Dm / BN, mtiles, 2), 256>>>(
        mem, Dm, 0, qW, Dm, 0, Qp, Dm, 0,
        LQ, Dm, Dm, 2, qb, nullptr, 0, 1.f, 0);

    // K = img @ kW + kb ; V = img @ vW + vb   (grid 7x49 = 343 blocks each)
    gemm_nn<<<dim3(Dm / BN, LK / BM, 1), 256>>>(
        img, Dm, 0, kW, Dm, 0, Kp, Dm, 0,
        LK, Dm, Dm, 1, kb, nullptr, 0, 1.f, 0);
    gemm_nn<<<dim3(Dm / BN, LK / BM, 1), 256>>>(
        img, Dm, 0, vW, Dm, 0, Vp, Dm, 0,
        LK, Dm, Dm, 1, vb, nullptr, 0, 1.f, 0);

    // scores[h] = Q_h @ K_h^T / sqrt(HD)   (batched over 8 heads)
    gemm_nt<<<dim3(LK / BN, mtiles, Hh), 256>>>(
        Qp, Dm, HDd, Kp, Dm, HDd,
        Sp, LK, (long long)LQ * LK,
        LQ, LK, HDd, inv_sqrt_hd);

    // in-place softmax over last dim
    softmax_kernel<<<Hh * LQ, 256>>>(Sp);

    // attn_sum[k] = sum over (h,q) probs
    colsum_kernel<<<dim3((LK + 255) / 256, 32), 256>>>(Sp, ASUMp, (Hh * LQ) / 32, Hh * LQ);

    // ctx[h] = probs[h] @ V_h   (N=112; split-K=8, atomic accumulate)
    gemm_nn<<<dim3(1, mtiles, Hh * 8), 256>>>(
        Sp, LK, (long long)LQ * LK, Vp, Dm, HDd, CTXp, Dm, HDd,
        LQ, HDd, LK, 8, nullptr, nullptr, 0, 1.f, 0);

    // T1 = ctx @ oW + ob + mem   (split-K=2)
    gemm_nn<<<dim3(Dm / BN, mtiles, 2), 256>>>(
        CTXp, Dm, 0, oW, Dm, 0, T1p, Dm, 0,
        LQ, Dm, Dm, 2, ob, mem, Dm, 1.f, 0);

    // attn_out = LN1(T1)
    layernorm_kernel<<<LQ, 224>>>(T1p, ln1g, ln1b, AOp);

    // hidden = relu(attn_out @ mW + mb)   (grid 28x13 = 364 blocks)
    gemm_nn<<<dim3(D4 / BN, mtiles, 1), 256>>>(
        AOp, Dm, 0, mW, D4, 0, HIDp, D4, 0,
        LQ, D4, Dm, 1, mb, nullptr, 0, 1.f, 1);

    // T1 = hidden @ pW + pb + attn_out   (split-K=2; re-zero T1 first)
    zero_kernel<<<(LQ * Dm + 255) / 256, 256>>>(T1p, LQ * Dm);
    gemm_nn<<<dim3(Dm / BN, mtiles, 2), 256>>>(
        HIDp, D4, 0, pW, Dm, 0, T1p, Dm, 0,
        LQ, Dm, D4, 2, pb, AOp, Dm, 1.f, 0);

    // out[0 : LQ*D] = LN2(T1)
    layernorm_kernel<<<LQ, 224>>>(T1p, ln2g, ln2b, out);

    // out[LQ*D : LQ*D+32] = frame scores
    frame_kernel<<<Ff, 256>>>(ASUMp, out + (size_t)LQ * Dm);
}

// round 5
// speedup vs baseline: 1.0616x; 1.0616x over previous
#include <cuda_runtime.h>
#include <math.h>

// ---------------- problem constants ----------------
#define Dm   896
#define Hh   8
#define HDd  112
#define Pp   196
#define Ff   32
#define LQ   1568           // M * P
#define LK   6272           // F * P
#define D4   3584           // 4 * D

typedef unsigned long long u64;

// ---------------- packed f32x2 helpers (Blackwell FFMA2) ----------------
__device__ __forceinline__ void ffma2(u64& d, u64 a, u64 b) {
    asm("fma.rn.f32x2 %0, %1, %2, %0;" : "+l"(d) : "l"(a), "l"(b));
}
__device__ __forceinline__ u64 dup2(float x) {
    u64 r; asm("mov.b64 %0, {%1, %1};" : "=l"(r) : "f"(x)); return r;
}
__device__ __forceinline__ void unpack2(u64 v, float& lo, float& hi) {
    asm("mov.b64 {%0, %1}, %2;" : "=f"(lo), "=f"(hi) : "l"(v));
}

// ---------------- scratch (device globals; no allocs allowed) ----------------
__device__ __align__(256) float g_Q  [LQ * Dm];
__device__ __align__(256) float g_K  [LK * Dm + 256];
__device__ __align__(256) float g_V  [LK * Dm + 256];
__device__ __align__(256) float g_S  [(size_t)Hh * LQ * LK];     // scores / probs, 314 MB
__device__ __align__(256) float g_CTX[LQ * Dm + 256];
__device__ __align__(256) float g_T1 [LQ * Dm];
__device__ __align__(256) float g_T2 [LQ * Dm];
__device__ __align__(256) float g_AO [LQ * Dm];
__device__ __align__(256) float g_HID[(size_t)LQ * D4 + 256];
__device__ __align__(256) float g_ASUM[LK];

// ---------------- reductions ----------------
__device__ __forceinline__ float warp_reduce_sum(float v) {
#pragma unroll
    for (int o = 16; o > 0; o >>= 1) v += __shfl_down_sync(0xffffffffu, v, o);
    return v;
}
__device__ __forceinline__ float warp_reduce_max(float v) {
#pragma unroll
    for (int o = 16; o > 0; o >>= 1) v = fmaxf(v, __shfl_down_sync(0xffffffffu, v, o));
    return v;
}
__device__ __forceinline__ float block_reduce_sum(float v, float* sred) {
    __syncthreads();
    v = warp_reduce_sum(v);
    if ((threadIdx.x & 31) == 0) sred[threadIdx.x >> 5] = v;
    __syncthreads();
    int nw = (blockDim.x + 31) >> 5;
    if (threadIdx.x < 32) {
        float x = (threadIdx.x < nw) ? sred[threadIdx.x] : 0.f;
        x = warp_reduce_sum(x);
        if (threadIdx.x == 0) sred[0] = x;
    }
    __syncthreads();
    return sred[0];
}
__device__ __forceinline__ float block_reduce_max(float v, float* sred) {
    __syncthreads();
    v = warp_reduce_max(v);
    if ((threadIdx.x & 31) == 0) sred[threadIdx.x >> 5] = v;
    __syncthreads();
    int nw = (blockDim.x + 31) >> 5;
    if (threadIdx.x < 32) {
        float x = (threadIdx.x < nw) ? sred[threadIdx.x] : -1e30f;
        x = warp_reduce_max(x);
        if (threadIdx.x == 0) sred[0] = x;
    }
    __syncthreads();
    return sred[0];
}

// ---------------- utility kernels ----------------
__global__ void zero_kernel(float* __restrict__ p, int n) {
    int i = blockIdx.x * blockDim.x + threadIdx.x;
    if (i < n) p[i] = 0.f;
}

// ---------------- SGEMM: 128x128x8, 256 threads, 8x8/thread, FFMA2 ----------------
#define BM 128
#define BN 128
#define BK 8

// C[batch] = act(alpha * A[batch] @ B[batch] + bias + res)
// A row-major [M,K] (lda), B row-major [K,N] (ldb).
// nsplit>1: K split across blockIdx.z%nsplit; partials atomicAdd into pre-zeroed C;
// bias/res contributed only by split 0; relu must be 0 then.
__global__ __launch_bounds__(256, 2)
void gemm_nn(const float* __restrict__ A, int lda, long long sAz,
             const float* __restrict__ B, int ldb, long long sBz,
             float* __restrict__ C, int ldc, long long sCz,
             int Md, int Nd, int Kd, int nsplit,
             const float* __restrict__ bias,
             const float* __restrict__ res, int ldres,
             float alpha, int relu)
{
    __shared__ float As[BK][BM + 4];
    __shared__ float Bs[BK][BN + 4];

    const int batch = blockIdx.z / nsplit;
    const int split = blockIdx.z % nsplit;
    A += (long long)batch * sAz;
    B += (long long)batch * sBz;
    C += (long long)batch * sCz;

    const int kLen = Kd / nsplit;
    const int kBeg = split * kLen;
    const int kEnd = kBeg + kLen;

    const int m0 = blockIdx.y * BM;
    const int n0 = blockIdx.x * BN;
    const int tid = threadIdx.x;
    const int tx = tid & 15;
    const int ty = tid >> 4;

    const int arow = tid >> 1;
    const int acol = (tid & 1) << 2;
    const int brow = tid >> 5;
    const int bcol = (tid & 31) << 2;

    u64 acc[8][4];
#pragma unroll
    for (int i = 0; i < 8; i++)
#pragma unroll
        for (int j = 0; j < 4; j++) acc[i][j] = 0ull;

    const bool arow_ok = (m0 + arow) < Md;
    const float* Abase = A + (long long)(m0 + arow) * lda + acol;
    const float* Bbase = B + n0 + bcol + (long long)brow * ldb;

    // prefetch first tile into registers
    float4 av = arow_ok ? *reinterpret_cast<const float4*>(Abase + kBeg)
                        : make_float4(0.f, 0.f, 0.f, 0.f);
    float4 bv = *reinterpret_cast<const float4*>(Bbase + (long long)kBeg * ldb);

    for (int k0 = kBeg; k0 < kEnd; k0 += BK) {
        As[acol + 0][arow] = av.x;
        As[acol + 1][arow] = av.y;
        As[acol + 2][arow] = av.z;
        As[acol + 3][arow] = av.w;
        *reinterpret_cast<float4*>(&Bs[brow][bcol]) = bv;
        __syncthreads();

        int kn = k0 + BK;
        if (kn < kEnd) {   // prefetch next tile while computing this one
            av = arow_ok ? *reinterpret_cast<const float4*>(Abase + kn)
                         : make_float4(0.f, 0.f, 0.f, 0.f);
            bv = *reinterpret_cast<const float4*>(Bbase + (long long)kn * ldb);
        }

#pragma unroll
        for (int kk = 0; kk < BK; kk++) {
            float ra[8];
            u64 rb[4];
            *reinterpret_cast<float4*>(&ra[0]) = *reinterpret_cast<const float4*>(&As[kk][ty * 8]);
            *reinterpret_cast<float4*>(&ra[4]) = *reinterpret_cast<const float4*>(&As[kk][ty * 8 + 4]);
            ulonglong2 blo = *reinterpret_cast<const ulonglong2*>(&Bs[kk][tx * 8]);
            ulonglong2 bhi = *reinterpret_cast<const ulonglong2*>(&Bs[kk][tx * 8 + 4]);
            rb[0] = blo.x; rb[1] = blo.y; rb[2] = bhi.x; rb[3] = bhi.y;
#pragma unroll
            for (int i = 0; i < 8; i++) {
                u64 a2 = dup2(ra[i]);
                ffma2(acc[i][0], a2, rb[0]);
                ffma2(acc[i][1], a2, rb[1]);
                ffma2(acc[i][2], a2, rb[2]);
                ffma2(acc[i][3], a2, rb[3]);
            }
        }
        __syncthreads();
    }

#pragma unroll
    for (int i = 0; i < 8; i++) {
        int m = m0 + ty * 8 + i;
        if (m >= Md) continue;
#pragma unroll
        for (int jp = 0; jp < 4; jp++) {
            float vlo, vhi;
            unpack2(acc[i][jp], vlo, vhi);
#pragma unroll
            for (int l = 0; l < 2; l++) {
                int n = n0 + tx * 8 + jp * 2 + l;
                if (n >= Nd) continue;
                float v = (l ? vhi : vlo) * alpha;
                if (nsplit > 1) {
                    if (split == 0) {
                        if (bias) v += bias[n];
                        if (res)  v += res[(long long)m * ldres + n];
                    }
                    atomicAdd(&C[(long long)m * ldc + n], v);
                } else {
                    if (bias) v += bias[n];
                    if (res)  v += res[(long long)m * ldres + n];
                    if (relu) v = fmaxf(v, 0.f);
                    C[(long long)m * ldc + n] = v;
                }
            }
        }
    }
}

// C[batch] = alpha * A[batch] @ B[batch]^T ; B row-major [N,K] (ldb)
__global__ __launch_bounds__(256, 2)
void gemm_nt(const float* __restrict__ A, int lda, long long sAz,
             const float* __restrict__ B, int ldb, long long sBz,
             float* __restrict__ C, int ldc, long long sCz,
             int Md, int Nd, int Kd, float alpha)
{
    __shared__ float As[BK][BM + 4];
    __shared__ float Bs[BK][BN + 4];

    const int batch = blockIdx.z;
    A += (long long)batch * sAz;
    B += (long long)batch * sBz;
    C += (long long)batch * sCz;

    const int m0 = blockIdx.y * BM;
    const int n0 = blockIdx.x * BN;
    const int tid = threadIdx.x;
    const int tx = tid & 15;
    const int ty = tid >> 4;

    const int arow = tid >> 1;
    const int acol = (tid & 1) << 2;

    u64 acc[8][4];
#pragma unroll
    for (int i = 0; i < 8; i++)
#pragma unroll
        for (int j = 0; j < 4; j++) acc[i][j] = 0ull;

    const bool arow_ok = (m0 + arow) < Md;
    const bool brow_ok = (n0 + arow) < Nd;
    const float* Abase = A + (long long)(m0 + arow) * lda + acol;
    const float* Bbase = B + (long long)(n0 + arow) * ldb + acol;

    float4 av = arow_ok ? *reinterpret_cast<const float4*>(Abase)
                        : make_float4(0.f, 0.f, 0.f, 0.f);
    float4 bv = brow_ok ? *reinterpret_cast<const float4*>(Bbase)
                        : make_float4(0.f, 0.f, 0.f, 0.f);

    for (int k0 = 0; k0 < Kd; k0 += BK) {
        As[acol + 0][arow] = av.x;
        As[acol + 1][arow] = av.y;
        As[acol + 2][arow] = av.z;
        As[acol + 3][arow] = av.w;
        Bs[acol + 0][arow] = bv.x;
        Bs[acol + 1][arow] = bv.y;
        Bs[acol + 2][arow] = bv.z;
        Bs[acol + 3][arow] = bv.w;
        __syncthreads();

        int kn = k0 + BK;
        if (kn < Kd) {
            av = arow_ok ? *reinterpret_cast<const float4*>(Abase + kn)
                         : make_float4(0.f, 0.f, 0.f, 0.f);
            bv = brow_ok ? *reinterpret_cast<const float4*>(Bbase + kn)
                         : make_float4(0.f, 0.f, 0.f, 0.f);
        }

#pragma unroll
        for (int kk = 0; kk < BK; kk++) {
            float ra[8];
            u64 rb[4];
            *reinterpret_cast<float4*>(&ra[0]) = *reinterpret_cast<const float4*>(&As[kk][ty * 8]);
            *reinterpret_cast<float4*>(&ra[4]) = *reinterpret_cast<const float4*>(&As[kk][ty * 8 + 4]);
            ulonglong2 blo = *reinterpret_cast<const ulonglong2*>(&Bs[kk][tx * 8]);
            ulonglong2 bhi = *reinterpret_cast<const ulonglong2*>(&Bs[kk][tx * 8 + 4]);
            rb[0] = blo.x; rb[1] = blo.y; rb[2] = bhi.x; rb[3] = bhi.y;
#pragma unroll
            for (int i = 0; i < 8; i++) {
                u64 a2 = dup2(ra[i]);
                ffma2(acc[i][0], a2, rb[0]);
                ffma2(acc[i][1], a2, rb[1]);
                ffma2(acc[i][2], a2, rb[2]);
                ffma2(acc[i][3], a2, rb[3]);
            }
        }
        __syncthreads();
    }

#pragma unroll
    for (int i = 0; i < 8; i++) {
        int m = m0 + ty * 8 + i;
        if (m >= Md) continue;
#pragma unroll
        for (int jp = 0; jp < 4; jp++) {
            float vlo, vhi;
            unpack2(acc[i][jp], vlo, vhi);
            int n = n0 + tx * 8 + jp * 2;
            if (n < Nd)     C[(long long)m * ldc + n]     = vlo * alpha;
            if (n + 1 < Nd) C[(long long)m * ldc + n + 1] = vhi * alpha;
        }
    }
}

// ---------------- softmax over rows of S (rowlen = LK), in place ----------------
__global__ __launch_bounds__(256)
void softmax_kernel(float* __restrict__ S)
{
    __shared__ float buf[LK];
    __shared__ float sred[32];
    float* p = S + (size_t)blockIdx.x * LK;
    const int t = threadIdx.x;

    float mx = -1e30f;
    for (int i = t; i < LK / 4; i += 256) {
        float4 v = reinterpret_cast<const float4*>(p)[i];
        reinterpret_cast<float4*>(buf)[i] = v;
        mx = fmaxf(fmaxf(mx, fmaxf(v.x, v.y)), fmaxf(v.z, v.w));
    }
    mx = block_reduce_max(mx, sred);

    float sum = 0.f;
    for (int i = t; i < LK / 4; i += 256) {
        float4 v = reinterpret_cast<const float4*>(buf)[i];
        v.x = __expf(v.x - mx);
        v.y = __expf(v.y - mx);
        v.z = __expf(v.z - mx);
        v.w = __expf(v.w - mx);
        reinterpret_cast<float4*>(buf)[i] = v;
        sum += (v.x + v.y) + (v.z + v.w);
    }
    sum = block_reduce_sum(sum, sred);
    float inv = 1.f / sum;
    for (int i = t; i < LK / 4; i += 256) {
        float4 v = reinterpret_cast<const float4*>(buf)[i];
        v.x *= inv; v.y *= inv; v.z *= inv; v.w *= inv;
        reinterpret_cast<float4*>(p)[i] = v;
    }
}

// ---------------- column sum of probs -> attn_sum (atomic partials) ----------------
__global__ void colsum_kernel(const float* __restrict__ S, float* __restrict__ asum,
                              int rows_per_chunk, int total_rows)
{
    int k = blockIdx.x * blockDim.x + threadIdx.x;
    if (k >= LK) return;
    int r0 = blockIdx.y * rows_per_chunk;
    int r1 = min(r0 + rows_per_chunk, total_rows);
    float s0 = 0.f, s1 = 0.f, s2 = 0.f, s3 = 0.f;
    int r = r0;
    for (; r + 4 <= r1; r += 4) {
        s0 += S[(size_t)(r + 0) * LK + k];
        s1 += S[(size_t)(r + 1) * LK + k];
        s2 += S[(size_t)(r + 2) * LK + k];
        s3 += S[(size_t)(r + 3) * LK + k];
    }
    for (; r < r1; r++) s0 += S[(size_t)r * LK + k];
    atomicAdd(&asum[k], (s0 + s1) + (s2 + s3));
}

// ---------------- layernorm over D=896 per row ----------------
__global__ __launch_bounds__(224)
void layernorm_kernel(const float* __restrict__ X, const float* __restrict__ g,
                      const float* __restrict__ b, float* __restrict__ Y)
{
    __shared__ float sred[32];
    const float* x = X + (size_t)blockIdx.x * Dm;
    float*       y = Y + (size_t)blockIdx.x * Dm;
    const int t = threadIdx.x;

    float4 xv = *reinterpret_cast<const float4*>(x + t * 4);
    float s = (xv.x + xv.y) + (xv.z + xv.w);
    s = block_reduce_sum(s, sred);
    float mu = s * (1.0f / Dm);

    float d0 = xv.x - mu, d1 = xv.y - mu, d2 = xv.z - mu, d3 = xv.w - mu;
    float sq = (d0 * d0 + d1 * d1) + (d2 * d2 + d3 * d3);
    sq = block_reduce_sum(sq, sred);
    float inv = rsqrtf(sq * (1.0f / Dm) + 1e-12f);

    float4 gv = *reinterpret_cast<const float4*>(g + t * 4);
    float4 bv = *reinterpret_cast<const float4*>(b + t * 4);
    float4 ov;
    ov.x = d0 * inv * gv.x + bv.x;
    ov.y = d1 * inv * gv.y + bv.y;
    ov.z = d2 * inv * gv.z + bv.z;
    ov.w = d3 * inv * gv.w + bv.w;
    *reinterpret_cast<float4*>(y + t * 4) = ov;
}

// ---------------- frame scores: mean over 196 per frame ----------------
__global__ void frame_kernel(const float* __restrict__ asum, float* __restrict__ out)
{
    __shared__ float red[256];
    int f = blockIdx.x;
    float s = 0.f;
    for (int i = threadIdx.x; i < Pp; i += blockDim.x) s += asum[f * Pp + i];
    red[threadIdx.x] = s;
    __syncthreads();
    for (int o = 128; o > 0; o >>= 1) {
        if (threadIdx.x < o) red[threadIdx.x] += red[threadIdx.x + o];
        __syncthreads();
    }
    if (threadIdx.x == 0) out[f] = red[0] * (1.0f / Pp);
}

// ---------------- host orchestration ----------------
extern "C" void kernel_launch(void* const* d_in, const int* in_sizes, int n_in,
                              void* d_out, int out_size)
{
    const float* img  = (const float*)d_in[0];
    const float* mem  = (const float*)d_in[1];
    const float* qW   = (const float*)d_in[2];
    const float* qb   = (const float*)d_in[3];
    const float* kW   = (const float*)d_in[4];
    const float* kb   = (const float*)d_in[5];
    const float* vW   = (const float*)d_in[6];
    const float* vb   = (const float*)d_in[7];
    const float* oW   = (const float*)d_in[8];
    const float* ob   = (const float*)d_in[9];
    const float* ln1g = (const float*)d_in[10];
    const float* ln1b = (const float*)d_in[11];
    const float* mW   = (const float*)d_in[12];
    const float* mb   = (const float*)d_in[13];
    const float* pW   = (const float*)d_in[14];
    const float* pb   = (const float*)d_in[15];
    const float* ln2g = (const float*)d_in[16];
    const float* ln2b = (const float*)d_in[17];
    float* out = (float*)d_out;

    float *Qp, *Kp, *Vp, *Sp, *CTXp, *T1p, *T2p, *AOp, *HIDp, *ASUMp;
    cudaGetSymbolAddress((void**)&Qp,   g_Q);
    cudaGetSymbolAddress((void**)&Kp,   g_K);
    cudaGetSymbolAddress((void**)&Vp,   g_V);
    cudaGetSymbolAddress((void**)&Sp,   g_S);
    cudaGetSymbolAddress((void**)&CTXp, g_CTX);
    cudaGetSymbolAddress((void**)&T1p,  g_T1);
    cudaGetSymbolAddress((void**)&T2p,  g_T2);
    cudaGetSymbolAddress((void**)&AOp,  g_AO);
    cudaGetSymbolAddress((void**)&HIDp, g_HID);
    cudaGetSymbolAddress((void**)&ASUMp,g_ASUM);

    const int mtiles = (LQ + BM - 1) / BM;   // 13
    const float inv_sqrt_hd = 0.09449111825230681f;  // 1/sqrt(112)

    // zero all atomic-accumulated buffers up front
    zero_kernel<<<(LQ * Dm + 255) / 256, 256>>>(Qp,   LQ * Dm);
    zero_kernel<<<(LQ * Dm + 255) / 256, 256>>>(CTXp, LQ * Dm);
    zero_kernel<<<(LQ * Dm + 255) / 256, 256>>>(T1p,  LQ * Dm);
    zero_kernel<<<(LQ * Dm + 255) / 256, 256>>>(T2p,  LQ * Dm);
    zero_kernel<<<(LK + 255) / 256, 256>>>(ASUMp, LK);

    // Q = mem @ qW + qb   (split-K=2 to fill SMs)
    gemm_nn<<<dim3(Dm / BN, mtiles, 2), 256>>>(
        mem, Dm, 0, qW, Dm, 0, Qp, Dm, 0,
        LQ, Dm, Dm, 2, qb, nullptr, 0, 1.f, 0);

    // K = img @ kW + kb ; V = img @ vW + vb
    gemm_nn<<<dim3(Dm / BN, LK / BM, 1), 256>>>(
        img, Dm, 0, kW, Dm, 0, Kp, Dm, 0,
        LK, Dm, Dm, 1, kb, nullptr, 0, 1.f, 0);
    gemm_nn<<<dim3(Dm / BN, LK / BM, 1), 256>>>(
        img, Dm, 0, vW, Dm, 0, Vp, Dm, 0,
        LK, Dm, Dm, 1, vb, nullptr, 0, 1.f, 0);

    // scores[h] = Q_h @ K_h^T / sqrt(HD)
    gemm_nt<<<dim3(LK / BN, mtiles, Hh), 256>>>(
        Qp, Dm, HDd, Kp, Dm, HDd,
        Sp, LK, (long long)LQ * LK,
        LQ, LK, HDd, inv_sqrt_hd);

    // in-place softmax over last dim
    softmax_kernel<<<Hh * LQ, 256>>>(Sp);

    // attn_sum[k] = sum over (h,q) probs
    colsum_kernel<<<dim3((LK + 255) / 256, 32), 256>>>(Sp, ASUMp, (Hh * LQ) / 32, Hh * LQ);

    // ctx[h] = probs[h] @ V_h   (N=112; split-K=8, atomic accumulate)
    gemm_nn<<<dim3(1, mtiles, Hh * 8), 256>>>(
        Sp, LK, (long long)LQ * LK, Vp, Dm, HDd, CTXp, Dm, HDd,
        LQ, HDd, LK, 8, nullptr, nullptr, 0, 1.f, 0);

    // T1 = ctx @ oW + ob + mem   (split-K=2)
    gemm_nn<<<dim3(Dm / BN, mtiles, 2), 256>>>(
        CTXp, Dm, 0, oW, Dm, 0, T1p, Dm, 0,
        LQ, Dm, Dm, 2, ob, mem, Dm, 1.f, 0);

    // attn_out = LN1(T1)
    layernorm_kernel<<<LQ, 224>>>(T1p, ln1g, ln1b, AOp);

    // hidden = relu(attn_out @ mW + mb)
    gemm_nn<<<dim3(D4 / BN, mtiles, 1), 256>>>(
        AOp, Dm, 0, mW, D4, 0, HIDp, D4, 0,
        LQ, D4, Dm, 1, mb, nullptr, 0, 1.f, 1);

    // T2 = hidden @ pW + pb + attn_out   (split-K=2, T2 pre-zeroed)
    gemm_nn<<<dim3(Dm / BN, mtiles, 2), 256>>>(
        HIDp, D4, 0, pW, Dm, 0, T2p, Dm, 0,
        LQ, Dm, D4, 2, pb, AOp, Dm, 1.f, 0);

    // out[0 : LQ*D] = LN2(T2)
    layernorm_kernel<<<LQ, 224>>>(T2p, ln2g, ln2b, out);

    // out[LQ*D : LQ*D+32] = frame scores
    frame_kernel<<<Ff, 256>>>(ASUMp, out + (size_t)LQ * Dm);
}